// round 8
// baseline (speedup 1.0000x reference)
#include <cuda_runtime.h>

#define BATCH 8
#define CIN   64
#define HH    128
#define WW    128
#define HWSZ  (HH * WW)
#define NGRP  8
#define CG    8
#define OG    8
#define OFFC  18

// deform tile geometry
#define TR    19          // tile rows: h0-5 .. h0+13 (8 output rows + |dy|<=5 margin + tap +-1)
#define TC    43          // tile cols used: w0-5 .. w0+37
#define TCP   44          // padded col stride (float2 units) -> kills r bank-alias
#define CSTR  (TR * TCP)  // per-channel float2 stride

__device__ float  g_off[BATCH * OFFC * HWSZ];   // offsets [b][18][h][w]
__device__ float4 g_w4[BATCH * 9 * HWSZ];       // (wy0*A, wy0*B, wy1*A, wy1*B)
__device__ unsigned g_meta[BATCH * 9 * HWSZ];   // y0c | y1c<<8 | xp<<16

// ---- packed f32x2 helpers (Blackwell) -------------------------------------
__device__ __forceinline__ unsigned long long pk2(float lo, float hi) {
    unsigned long long r;
    asm("mov.b64 %0, {%1,%2};" : "=l"(r) : "f"(lo), "f"(hi));
    return r;
}
__device__ __forceinline__ void upk2(unsigned long long v, float& lo, float& hi) {
    asm("mov.b64 {%0,%1}, %2;" : "=f"(lo), "=f"(hi) : "l"(v));
}
__device__ __forceinline__ unsigned long long ffma2(
    unsigned long long a, unsigned long long b, unsigned long long c) {
    unsigned long long d;
    asm("fma.rn.f32x2 %0, %1, %2, %3;" : "=l"(d) : "l"(a), "l"(b), "l"(c));
    return d;
}

// ---------------------------------------------------------------------------
// Kernel 1: offset conv (64ch -> 18ch, 3x3, pad 1) + PReLU.
// Block (32,8): 1 row x 18 outputs per thread. grid (4,16,8) = 512 blocks.
// ---------------------------------------------------------------------------
__global__ __launch_bounds__(256) void offset_conv_kernel(
    const float* __restrict__ x, const float* __restrict__ ow,
    const float* __restrict__ ob, const float* __restrict__ pa)
{
    __shared__ __align__(16) float ws[CIN * 9 * 20];   // [c][tap][20], 46080 B

    int tx = threadIdx.x, ty = threadIdx.y;
    int tid = ty * 32 + tx;
    for (int i = tid; i < CIN * 9 * 18; i += 256) {
        int c = i / 162;
        int r = i - c * 162;
        int tap = r / 18;
        int j = r - tap * 18;
        ws[(c * 9 + tap) * 20 + j] = ow[j * (CIN * 9) + c * 9 + tap];
    }
    __syncthreads();

    int b  = blockIdx.z;
    int w0 = blockIdx.x * 32 + tx;
    int h0 = blockIdx.y * 8 + ty;

    bool vr[3], vc[3];
#pragma unroll
    for (int r = 0; r < 3; r++) vr[r] = (unsigned)(h0 - 1 + r) < (unsigned)HH;
#pragma unroll
    for (int cc = 0; cc < 3; cc++) vc[cc] = (unsigned)(w0 - 1 + cc) < (unsigned)WW;

    unsigned long long acc2[9];
#pragma unroll
    for (int jj = 0; jj < 9; jj++)
        acc2[jj] = pk2(ob[2 * jj], ob[2 * jj + 1]);

    const float* xbase = x + ((size_t)(b * CIN) * HH + (h0 - 1)) * WW + (w0 - 1);

    for (int c = 0; c < CIN; c++) {
        const float* px = xbase + c * HWSZ;
        float xv[3][3];
#pragma unroll
        for (int r = 0; r < 3; r++)
#pragma unroll
            for (int cc = 0; cc < 3; cc++)
                xv[r][cc] = (vr[r] && vc[cc]) ? __ldg(px + r * WW + cc) : 0.f;

        const float* wrow = &ws[c * 180];
#pragma unroll
        for (int tap = 0; tap < 9; tap++) {
            const char* wp = (const char*)(wrow + tap * 20);
            ulonglong2 q0 = *(const ulonglong2*)(wp);
            ulonglong2 q1 = *(const ulonglong2*)(wp + 16);
            ulonglong2 q2 = *(const ulonglong2*)(wp + 32);
            ulonglong2 q3 = *(const ulonglong2*)(wp + 48);
            unsigned long long q8 = *(const unsigned long long*)(wp + 64);
            unsigned long long wj[9] = {q0.x, q0.y, q1.x, q1.y,
                                        q2.x, q2.y, q3.x, q3.y, q8};
            int ky = tap / 3;
            int kx = tap - ky * 3;
            unsigned long long a0 = pk2(xv[ky][kx], xv[ky][kx]);
#pragma unroll
            for (int jj = 0; jj < 9; jj++)
                acc2[jj] = ffma2(a0, wj[jj], acc2[jj]);
        }
    }

    float a = pa[0];
#pragma unroll
    for (int jj = 0; jj < 9; jj++) {
        float v0, v1;
        upk2(acc2[jj], v0, v1);
        v0 = v0 > 0.f ? v0 : a * v0;
        v1 = v1 > 0.f ? v1 : a * v1;
        g_off[((b * OFFC + 2 * jj)     * HH + h0) * WW + w0] = v0;
        g_off[((b * OFFC + 2 * jj + 1) * HH + h0) * WW + w0] = v1;
    }
}

// ---------------------------------------------------------------------------
// Kernel 2: bilinear precompute with pair-remapped x weights.
// contribution = wy0*(A*v[y0c][xp]+B*v[y0c][xp+1]) + wy1*(A*v[y1c][xp]+B*v[y1c][xp+1])
// ---------------------------------------------------------------------------
__global__ __launch_bounds__(256) void bilin_kernel()
{
    int idx = blockIdx.x * 256 + threadIdx.x;
    const int total = BATCH * 9 * HWSZ;
    if (idx >= total) return;
    int w = idx & 127;
    int t = idx >> 7;
    int h = t & 127;
    int bk = t >> 7;
    int k = bk % 9;
    int b = bk / 9;

    float dy = g_off[((b * OFFC + 2 * k)     * HH + h) * WW + w];
    float dx = g_off[((b * OFFC + 2 * k + 1) * HH + h) * WW + w];
    int ky = k / 3 - 1;
    int kx = k - (k / 3) * 3 - 1;
    float py = (float)(h + ky) + dy;
    float px = (float)(w + kx) + dx;
    float y0f = floorf(py), x0f = floorf(px);
    float ly = py - y0f, lx = px - x0f;
    int y0 = (int)y0f, x0 = (int)x0f;
    float hy = 1.f - ly, hx = 1.f - lx;

    float wy0 = ((unsigned)y0       < (unsigned)HH) ? hy : 0.f;
    float wy1 = ((unsigned)(y0 + 1) < (unsigned)HH) ? ly : 0.f;
    float wx0 = ((unsigned)x0       < (unsigned)WW) ? hx : 0.f;
    float wx1 = ((unsigned)(x0 + 1) < (unsigned)WW) ? lx : 0.f;

    int xp; float A, B;
    if (x0 < 0)        { xp = 0;   A = wx1; B = 0.f; }
    else if (x0 > 126) { xp = 126; A = 0.f; B = wx0; }
    else               { xp = x0;  A = wx0; B = wx1; }

    int y0c = min(max(y0, 0), HH - 1);
    int y1c = min(max(y0 + 1, 0), HH - 1);

    g_w4[idx]   = make_float4(wy0 * A, wy0 * B, wy1 * A, wy1 * B);
    g_meta[idx] = (unsigned)y0c | ((unsigned)y1c << 8) | ((unsigned)xp << 16);
}

// ---------------------------------------------------------------------------
// Kernel 3: grouped deformable conv, smem pair-tile version.
// grid (4 xchunks, 16 hchunks, 64 = b*8+g); block (32,8): 32 px x 8 rows.
// Tile: tile2[8ch][19 rows][44 pad cols] float2 duplicated pairs (53.5KB)
//  -> 4 blocks/SM. Row stride 352B breaks the r bank-alias.
// ---------------------------------------------------------------------------
__global__ __launch_bounds__(256) void deform_kernel(
    const float* __restrict__ x, const float* __restrict__ dw,
    const float* __restrict__ db, float* __restrict__ out)
{
    extern __shared__ __align__(16) char dsm[];
    float2* tile2 = (float2*)dsm;                        // 8*19*44 f2 = 53504B
    float*  s_w   = (float*)(dsm + CG * CSTR * 8);       // 2304B

    int tx = threadIdx.x;
    int ty = threadIdx.y;
    int tid = ty * 32 + tx;
    int bz = blockIdx.z;
    int b = bz >> 3;
    int g = bz & 7;
    int w0 = blockIdx.x * 32;
    int h0 = blockIdx.y * 8;

    // stage weights: s_w[k][c][oo]
    for (int i = tid; i < 9 * CG * OG; i += 256) {
        int k  = i >> 6;
        int rc = i & 63;
        int c  = rc >> 3;
        int oo = rc & 7;
        s_w[i] = dw[((g * 8 + oo) * 8 + c) * 9 + k];
    }

    // stage tile: tile2[c][r][j] = (v[gx], v[min(gx+1,127)]), gx = clamp(w0-5+j)
    const float* xg = x + (size_t)(b * CIN + g * CG) * HWSZ;
    for (int i = tid; i < CG * TR * TCP; i += 256) {
        int c  = i / (TR * TCP);
        int rj = i - c * (TR * TCP);
        int r  = rj / TCP;
        int j  = rj - r * TCP;
        if (j < TC) {
            int gy = min(max(h0 - 5 + r, 0), HH - 1);
            int gx = min(max(w0 - 5 + j, 0), WW - 1);
            int gxn = min(gx + 1, WW - 1);
            const float* row = xg + c * HWSZ + gy * WW;
            tile2[c * CSTR + r * TCP + j] = make_float2(row[gx], row[gxn]);
        }
    }
    __syncthreads();

    int h  = h0 + ty;
    int px = w0 + tx;

    unsigned long long acc2[4];
#pragma unroll
    for (int q = 0; q < 4; q++)
        acc2[q] = pk2(db[g * 8 + 2 * q], db[g * 8 + 2 * q + 1]);

#pragma unroll 1
    for (int k = 0; k < 9; k++) {
        int midx = ((b * 9 + k) * HH + h) * WW + px;
        float4 w4 = __ldg(&g_w4[midx]);
        unsigned meta = __ldg(&g_meta[midx]);
        int y0c =  meta        & 255;
        int y1c = (meta >> 8)  & 255;
        int xp  =  meta >> 16;
        int r0 = y0c - (h0 - 5);
        int r1 = y1c - (h0 - 5);
        int xq = xp - (w0 - 5);
        bool inx = (unsigned)xq < (unsigned)TC;
        bool in0 = inx && (unsigned)r0 < (unsigned)TR;
        bool in1 = inx && (unsigned)r1 < (unsigned)TR;
        int t0 = r0 * TCP + xq;
        int t1 = r1 * TCP + xq;
        const float* f0 = xg + y0c * WW + xp;   // rare fallback
        const float* f1 = xg + y1c * WW + xp;

        const float* wk = &s_w[k * 64];
#pragma unroll
        for (int c = 0; c < 8; c++) {
            float2 P0, P1;
            if (in0) P0 = tile2[c * CSTR + t0];
            else     P0 = make_float2(__ldg(f0 + c * HWSZ), __ldg(f0 + c * HWSZ + 1));
            if (in1) P1 = tile2[c * CSTR + t1];
            else     P1 = make_float2(__ldg(f1 + c * HWSZ), __ldg(f1 + c * HWSZ + 1));
            float v = w4.x * P0.x + w4.y * P0.y + w4.z * P1.x + w4.w * P1.y;
            ulonglong2 u0 = *(const ulonglong2*)(wk + c * 8);
            ulonglong2 u1 = *(const ulonglong2*)(wk + c * 8 + 4);
            unsigned long long v2 = pk2(v, v);
            acc2[0] = ffma2(v2, u0.x, acc2[0]);
            acc2[1] = ffma2(v2, u0.y, acc2[1]);
            acc2[2] = ffma2(v2, u1.x, acc2[2]);
            acc2[3] = ffma2(v2, u1.y, acc2[3]);
        }
    }

#pragma unroll
    for (int q = 0; q < 4; q++) {
        float v0, v1;
        upk2(acc2[q], v0, v1);
        out[((b * CIN + g * 8 + 2 * q)     * HH + h) * WW + px] = v0;
        out[((b * CIN + g * 8 + 2 * q + 1) * HH + h) * WW + px] = v1;
    }
}

// ---------------------------------------------------------------------------
extern "C" void kernel_launch(void* const* d_in, const int* in_sizes, int n_in,
                              void* d_out, int out_size)
{
    const float* x  = (const float*)d_in[0];
    const float* ow = (const float*)d_in[1];
    const float* ob = (const float*)d_in[2];
    const float* pa = (const float*)d_in[3];
    const float* dw = (const float*)d_in[4];
    const float* db = (const float*)d_in[5];
    float* out = (float*)d_out;

    const int dyn = CG * CSTR * 8 + 9 * CG * OG * 4;   // 53504 + 2304 = 55808 B
    cudaFuncSetAttribute(deform_kernel,
                         cudaFuncAttributeMaxDynamicSharedMemorySize, dyn);

    offset_conv_kernel<<<dim3(4, 16, 8), dim3(32, 8)>>>(x, ow, ob, pa);
    const int totB = BATCH * 9 * HWSZ;
    bilin_kernel<<<(totB + 255) / 256, 256>>>();
    deform_kernel<<<dim3(4, 16, 64), dim3(32, 8), dyn>>>(x, dw, db, out);
}

// round 9
// speedup vs baseline: 1.1211x; 1.1211x over previous
#include <cuda_runtime.h>

#define BATCH 8
#define CIN   64
#define HH    128
#define WW    128
#define HWSZ  (HH * WW)
#define NGRP  8
#define CG    8
#define OG    8
#define OFFC  18

__device__ float  g_off[BATCH * OFFC * HWSZ];    // offsets [b][18][h][w]
__device__ float4 g_w4[BATCH * 9 * HWSZ];        // (wy0*A, wy0*B, wy1*A, wy1*B)
__device__ unsigned g_meta[BATCH * 9 * HWSZ];    // y0c | y1c<<8 | xp<<16
__device__ float2 g_xdup[BATCH * CIN * HWSZ];    // (v[x], v[x+1]) pairs, 67MB

// ---- packed f32x2 helpers (Blackwell) -------------------------------------
__device__ __forceinline__ unsigned long long pk2(float lo, float hi) {
    unsigned long long r;
    asm("mov.b64 %0, {%1,%2};" : "=l"(r) : "f"(lo), "f"(hi));
    return r;
}
__device__ __forceinline__ void upk2(unsigned long long v, float& lo, float& hi) {
    asm("mov.b64 {%0,%1}, %2;" : "=f"(lo), "=f"(hi) : "l"(v));
}
__device__ __forceinline__ unsigned long long ffma2(
    unsigned long long a, unsigned long long b, unsigned long long c) {
    unsigned long long d;
    asm("fma.rn.f32x2 %0, %1, %2, %3;" : "=l"(d) : "l"(a), "l"(b), "l"(c));
    return d;
}

// ---------------------------------------------------------------------------
// Kernel 0: duplicated-pair relayout: xdup[i] = (x[i], x[i+1 or clamp])
// ---------------------------------------------------------------------------
__global__ __launch_bounds__(256) void dup_kernel(const float* __restrict__ x)
{
    int idx = blockIdx.x * 256 + threadIdx.x;
    if (idx >= BATCH * CIN * HWSZ) return;
    int w = idx & 127;
    float v  = x[idx];
    float vn = (w < 127) ? x[idx + 1] : v;
    g_xdup[idx] = make_float2(v, vn);
}

// ---------------------------------------------------------------------------
// Kernel 1: offset conv (64ch -> 18ch, 3x3, pad 1) + PReLU.
// Block (32,4), 2 rows x 18 outputs per thread (best measured variant).
// ---------------------------------------------------------------------------
__global__ __launch_bounds__(128) void offset_conv_kernel(
    const float* __restrict__ x, const float* __restrict__ ow,
    const float* __restrict__ ob, const float* __restrict__ pa)
{
    __shared__ __align__(16) float ws[CIN * 9 * 20];   // [c][tap][20], 46080 B

    int tx = threadIdx.x, ty = threadIdx.y;
    int tid = ty * 32 + tx;
    for (int i = tid; i < CIN * 9 * 18; i += 128) {
        int c = i / 162;
        int r = i - c * 162;
        int tap = r / 18;
        int j = r - tap * 18;
        ws[(c * 9 + tap) * 20 + j] = ow[j * (CIN * 9) + c * 9 + tap];
    }
    __syncthreads();

    int b  = blockIdx.z;
    int w0 = blockIdx.x * 32 + tx;
    int h0 = blockIdx.y * 8 + ty * 2;

    bool vr[4], vc[3];
#pragma unroll
    for (int r = 0; r < 4; r++) vr[r] = (unsigned)(h0 - 1 + r) < (unsigned)HH;
#pragma unroll
    for (int cc = 0; cc < 3; cc++) vc[cc] = (unsigned)(w0 - 1 + cc) < (unsigned)WW;

    unsigned long long acc2[2][9];
#pragma unroll
    for (int jj = 0; jj < 9; jj++) {
        unsigned long long t = pk2(ob[2 * jj], ob[2 * jj + 1]);
        acc2[0][jj] = t;
        acc2[1][jj] = t;
    }

    const float* xbase = x + ((size_t)(b * CIN) * HH + (h0 - 1)) * WW + (w0 - 1);

    for (int c = 0; c < CIN; c++) {
        const float* px = xbase + c * HWSZ;
        float xv[4][3];
#pragma unroll
        for (int r = 0; r < 4; r++)
#pragma unroll
            for (int cc = 0; cc < 3; cc++)
                xv[r][cc] = (vr[r] && vc[cc]) ? __ldg(px + r * WW + cc) : 0.f;

        const float* wrow = &ws[c * 180];
#pragma unroll
        for (int tap = 0; tap < 9; tap++) {
            const char* wp = (const char*)(wrow + tap * 20);
            ulonglong2 q0 = *(const ulonglong2*)(wp);
            ulonglong2 q1 = *(const ulonglong2*)(wp + 16);
            ulonglong2 q2 = *(const ulonglong2*)(wp + 32);
            ulonglong2 q3 = *(const ulonglong2*)(wp + 48);
            unsigned long long q8 = *(const unsigned long long*)(wp + 64);
            unsigned long long wj[9] = {q0.x, q0.y, q1.x, q1.y,
                                        q2.x, q2.y, q3.x, q3.y, q8};
            int ky = tap / 3;
            int kx = tap - ky * 3;
            unsigned long long a0 = pk2(xv[ky][kx],     xv[ky][kx]);
            unsigned long long a1 = pk2(xv[ky + 1][kx], xv[ky + 1][kx]);
#pragma unroll
            for (int jj = 0; jj < 9; jj++) {
                acc2[0][jj] = ffma2(a0, wj[jj], acc2[0][jj]);
                acc2[1][jj] = ffma2(a1, wj[jj], acc2[1][jj]);
            }
        }
    }

    float a = pa[0];
#pragma unroll
    for (int i = 0; i < 2; i++)
#pragma unroll
        for (int jj = 0; jj < 9; jj++) {
            float v0, v1;
            upk2(acc2[i][jj], v0, v1);
            v0 = v0 > 0.f ? v0 : a * v0;
            v1 = v1 > 0.f ? v1 : a * v1;
            int hrow = h0 + i;
            g_off[((b * OFFC + 2 * jj)     * HH + hrow) * WW + w0] = v0;
            g_off[((b * OFFC + 2 * jj + 1) * HH + hrow) * WW + w0] = v1;
        }
}

// ---------------------------------------------------------------------------
// Kernel 2: bilinear precompute with pair-remapped x weights.
// contribution = wy0*(A*v[y0c][xp]+B*v[y0c][xp+1]) + wy1*(A*v[y1c][xp]+B*v[y1c][xp+1])
// ---------------------------------------------------------------------------
__global__ __launch_bounds__(256) void bilin_kernel()
{
    int idx = blockIdx.x * 256 + threadIdx.x;
    if (idx >= BATCH * 9 * HWSZ) return;
    int w = idx & 127;
    int t = idx >> 7;
    int h = t & 127;
    int bk = t >> 7;
    int k = bk % 9;
    int b = bk / 9;

    float dy = g_off[((b * OFFC + 2 * k)     * HH + h) * WW + w];
    float dx = g_off[((b * OFFC + 2 * k + 1) * HH + h) * WW + w];
    int ky = k / 3 - 1;
    int kx = k - (k / 3) * 3 - 1;
    float py = (float)(h + ky) + dy;
    float px = (float)(w + kx) + dx;
    float y0f = floorf(py), x0f = floorf(px);
    float ly = py - y0f, lx = px - x0f;
    int y0 = (int)y0f, x0 = (int)x0f;
    float hy = 1.f - ly, hx = 1.f - lx;

    float wy0 = ((unsigned)y0       < (unsigned)HH) ? hy : 0.f;
    float wy1 = ((unsigned)(y0 + 1) < (unsigned)HH) ? ly : 0.f;
    float wx0 = ((unsigned)x0       < (unsigned)WW) ? hx : 0.f;
    float wx1 = ((unsigned)(x0 + 1) < (unsigned)WW) ? lx : 0.f;

    int xp; float A, B;
    if (x0 < 0)        { xp = 0;   A = wx1; B = 0.f; }
    else if (x0 > 126) { xp = 126; A = 0.f; B = wx0; }
    else               { xp = x0;  A = wx0; B = wx1; }

    int y0c = min(max(y0, 0), HH - 1);
    int y1c = min(max(y0 + 1, 0), HH - 1);

    g_w4[idx]   = make_float4(wy0 * A, wy0 * B, wy1 * A, wy1 * B);
    g_meta[idx] = (unsigned)y0c | ((unsigned)y1c << 8) | ((unsigned)xp << 16);
}

// ---------------------------------------------------------------------------
// Kernel 3: grouped deformable conv — R3 gather structure, but each
// (corner-row, channel) gather is ONE aligned LDG.64 from the dup-pair array.
// grid (H, B); block (32, 8 groups); 4 px per thread.
// ---------------------------------------------------------------------------
__global__ __launch_bounds__(256) void deform_kernel(
    const float* __restrict__ dw, const float* __restrict__ db,
    float* __restrict__ out)
{
    __shared__ __align__(16) float s_w[NGRP * 9 * CG * OG];  // [g][k][c][oo]

    int tx = threadIdx.x;
    int g  = threadIdx.y;
    int tid = g * 32 + tx;
    int b = blockIdx.y;
    int h = blockIdx.x;

    for (int i = tid; i < NGRP * 9 * CG * OG; i += 256) {
        int gg = i / 576;
        int r  = i - gg * 576;
        int k  = r >> 6;
        int rc = r & 63;
        int c  = rc >> 3;
        int oo = rc & 7;
        s_w[i] = dw[((gg * 8 + oo) * 8 + c) * 9 + k];
    }
    __syncthreads();

    const float2* xd = g_xdup + (size_t)(b * CIN + g * CG) * HWSZ;

    unsigned long long acc2[4][4];
#pragma unroll
    for (int q = 0; q < 4; q++) {
        unsigned long long t = pk2(db[g * 8 + 2 * q], db[g * 8 + 2 * q + 1]);
        acc2[0][q] = t; acc2[1][q] = t; acc2[2][q] = t; acc2[3][q] = t;
    }

#pragma unroll 1
    for (int k = 0; k < 9; k++) {
        float4 w4[4];
        int off0[4], off1[4];
#pragma unroll
        for (int p = 0; p < 4; p++) {
            int wp = tx + 32 * p;
            int midx = ((b * 9 + k) * HH + h) * WW + wp;
            w4[p] = __ldg(&g_w4[midx]);
            unsigned meta = __ldg(&g_meta[midx]);
            int y0c =  meta        & 255;
            int y1c = (meta >> 8)  & 255;
            int xp  =  meta >> 16;
            off0[p] = (y0c << 7) + xp;
            off1[p] = (y1c << 7) + xp;
        }
        const float* wk = &s_w[(g * 9 + k) * 64];
#pragma unroll
        for (int c = 0; c < 8; c++) {
            ulonglong2 u0 = *(const ulonglong2*)(wk + c * 8);
            ulonglong2 u1 = *(const ulonglong2*)(wk + c * 8 + 4);
            const float2* xc = xd + c * HWSZ;
#pragma unroll
            for (int p = 0; p < 4; p++) {
                float2 P0 = __ldg(xc + off0[p]);
                float2 P1 = __ldg(xc + off1[p]);
                float v = w4[p].x * P0.x + w4[p].y * P0.y +
                          w4[p].z * P1.x + w4[p].w * P1.y;
                unsigned long long v2 = pk2(v, v);
                acc2[p][0] = ffma2(v2, u0.x, acc2[p][0]);
                acc2[p][1] = ffma2(v2, u0.y, acc2[p][1]);
                acc2[p][2] = ffma2(v2, u1.x, acc2[p][2]);
                acc2[p][3] = ffma2(v2, u1.y, acc2[p][3]);
            }
        }
    }

#pragma unroll
    for (int q = 0; q < 4; q++)
#pragma unroll
        for (int p = 0; p < 4; p++) {
            float v0, v1;
            upk2(acc2[p][q], v0, v1);
            int wp = tx + 32 * p;
            out[((b * CIN + g * 8 + 2 * q)     * HH + h) * WW + wp] = v0;
            out[((b * CIN + g * 8 + 2 * q + 1) * HH + h) * WW + wp] = v1;
        }
}

// ---------------------------------------------------------------------------
extern "C" void kernel_launch(void* const* d_in, const int* in_sizes, int n_in,
                              void* d_out, int out_size)
{
    const float* x  = (const float*)d_in[0];
    const float* ow = (const float*)d_in[1];
    const float* ob = (const float*)d_in[2];
    const float* pa = (const float*)d_in[3];
    const float* dw = (const float*)d_in[4];
    const float* db = (const float*)d_in[5];
    float* out = (float*)d_out;

    const int totX = BATCH * CIN * HWSZ;
    dup_kernel<<<(totX + 255) / 256, 256>>>(x);
    offset_conv_kernel<<<dim3(4, 16, 8), dim3(32, 4)>>>(x, ow, ob, pa);
    const int totB = BATCH * 9 * HWSZ;
    bilin_kernel<<<(totB + 255) / 256, 256>>>();
    deform_kernel<<<dim3(HH, BATCH), dim3(32, 8)>>>(dw, db, out);
}

// round 11
// speedup vs baseline: 1.3434x; 1.1984x over previous
#include <cuda_runtime.h>

#define BATCH 8
#define CIN   64
#define HH    128
#define WW    128
#define HWSZ  (HH * WW)
#define NGRP  8
#define CG    8
#define OG    8
#define OFFC  18

__device__ float  g_off[BATCH * OFFC * HWSZ];    // offsets [b][18][h][w]
__device__ float4 g_w4[BATCH * 9 * HWSZ];        // (wy0*A, wy0*B, wy1*A, wy1*B)
__device__ unsigned g_meta[BATCH * 9 * HWSZ];    // y0c | y1c<<8 | xp<<16

// ---- packed f32x2 helpers (Blackwell) -------------------------------------
__device__ __forceinline__ unsigned long long pk2(float lo, float hi) {
    unsigned long long r;
    asm("mov.b64 %0, {%1,%2};" : "=l"(r) : "f"(lo), "f"(hi));
    return r;
}
__device__ __forceinline__ void upk2(unsigned long long v, float& lo, float& hi) {
    asm("mov.b64 {%0,%1}, %2;" : "=f"(lo), "=f"(hi) : "l"(v));
}
__device__ __forceinline__ unsigned long long ffma2(
    unsigned long long a, unsigned long long b, unsigned long long c) {
    unsigned long long d;
    asm("fma.rn.f32x2 %0, %1, %2, %3;" : "=l"(d) : "l"(a), "l"(b), "l"(c));
    return d;
}

// ---------------------------------------------------------------------------
// Kernel 1: offset conv (64ch -> 18ch, 3x3, pad 1) + PReLU.
// Block (32,4), 2 rows x 18 outputs per thread (best measured variant).
// ---------------------------------------------------------------------------
__global__ __launch_bounds__(128) void offset_conv_kernel(
    const float* __restrict__ x, const float* __restrict__ ow,
    const float* __restrict__ ob, const float* __restrict__ pa)
{
    __shared__ __align__(16) float ws[CIN * 9 * 20];   // [c][tap][20], 46080 B

    int tx = threadIdx.x, ty = threadIdx.y;
    int tid = ty * 32 + tx;
    for (int i = tid; i < CIN * 9 * 18; i += 128) {
        int c = i / 162;
        int r = i - c * 162;
        int tap = r / 18;
        int j = r - tap * 18;
        ws[(c * 9 + tap) * 20 + j] = ow[j * (CIN * 9) + c * 9 + tap];
    }
    __syncthreads();

    int b  = blockIdx.z;
    int w0 = blockIdx.x * 32 + tx;
    int h0 = blockIdx.y * 8 + ty * 2;

    bool vr[4], vc[3];
#pragma unroll
    for (int r = 0; r < 4; r++) vr[r] = (unsigned)(h0 - 1 + r) < (unsigned)HH;
#pragma unroll
    for (int cc = 0; cc < 3; cc++) vc[cc] = (unsigned)(w0 - 1 + cc) < (unsigned)WW;

    unsigned long long acc2[2][9];
#pragma unroll
    for (int jj = 0; jj < 9; jj++) {
        unsigned long long t = pk2(ob[2 * jj], ob[2 * jj + 1]);
        acc2[0][jj] = t;
        acc2[1][jj] = t;
    }

    const float* xbase = x + ((size_t)(b * CIN) * HH + (h0 - 1)) * WW + (w0 - 1);

    for (int c = 0; c < CIN; c++) {
        const float* px = xbase + c * HWSZ;
        float xv[4][3];
#pragma unroll
        for (int r = 0; r < 4; r++)
#pragma unroll
            for (int cc = 0; cc < 3; cc++)
                xv[r][cc] = (vr[r] && vc[cc]) ? __ldg(px + r * WW + cc) : 0.f;

        const float* wrow = &ws[c * 180];
#pragma unroll
        for (int tap = 0; tap < 9; tap++) {
            const char* wp = (const char*)(wrow + tap * 20);
            ulonglong2 q0 = *(const ulonglong2*)(wp);
            ulonglong2 q1 = *(const ulonglong2*)(wp + 16);
            ulonglong2 q2 = *(const ulonglong2*)(wp + 32);
            ulonglong2 q3 = *(const ulonglong2*)(wp + 48);
            unsigned long long q8 = *(const unsigned long long*)(wp + 64);
            unsigned long long wj[9] = {q0.x, q0.y, q1.x, q1.y,
                                        q2.x, q2.y, q3.x, q3.y, q8};
            int ky = tap / 3;
            int kx = tap - ky * 3;
            unsigned long long a0 = pk2(xv[ky][kx],     xv[ky][kx]);
            unsigned long long a1 = pk2(xv[ky + 1][kx], xv[ky + 1][kx]);
#pragma unroll
            for (int jj = 0; jj < 9; jj++) {
                acc2[0][jj] = ffma2(a0, wj[jj], acc2[0][jj]);
                acc2[1][jj] = ffma2(a1, wj[jj], acc2[1][jj]);
            }
        }
    }

    float a = pa[0];
#pragma unroll
    for (int i = 0; i < 2; i++)
#pragma unroll
        for (int jj = 0; jj < 9; jj++) {
            float v0, v1;
            upk2(acc2[i][jj], v0, v1);
            v0 = v0 > 0.f ? v0 : a * v0;
            v1 = v1 > 0.f ? v1 : a * v1;
            int hrow = h0 + i;
            g_off[((b * OFFC + 2 * jj)     * HH + hrow) * WW + w0] = v0;
            g_off[((b * OFFC + 2 * jj + 1) * HH + hrow) * WW + w0] = v1;
        }
}

// ---------------------------------------------------------------------------
// Kernel 2: bilinear precompute with pair-remapped x weights.
// contribution = wy0*(A*v[y0c][xp]+B*v[y0c][xp+1]) + wy1*(A*v[y1c][xp]+B*v[y1c][xp+1])
// ---------------------------------------------------------------------------
__global__ __launch_bounds__(256) void bilin_kernel()
{
    int idx = blockIdx.x * 256 + threadIdx.x;
    if (idx >= BATCH * 9 * HWSZ) return;
    int w = idx & 127;
    int t = idx >> 7;
    int h = t & 127;
    int bk = t >> 7;
    int k = bk % 9;
    int b = bk / 9;

    float dy = g_off[((b * OFFC + 2 * k)     * HH + h) * WW + w];
    float dx = g_off[((b * OFFC + 2 * k + 1) * HH + h) * WW + w];
    int ky = k / 3 - 1;
    int kx = k - (k / 3) * 3 - 1;
    float py = (float)(h + ky) + dy;
    float px = (float)(w + kx) + dx;
    float y0f = floorf(py), x0f = floorf(px);
    float ly = py - y0f, lx = px - x0f;
    int y0 = (int)y0f, x0 = (int)x0f;
    float hy = 1.f - ly, hx = 1.f - lx;

    float wy0 = ((unsigned)y0       < (unsigned)HH) ? hy : 0.f;
    float wy1 = ((unsigned)(y0 + 1) < (unsigned)HH) ? ly : 0.f;
    float wx0 = ((unsigned)x0       < (unsigned)WW) ? hx : 0.f;
    float wx1 = ((unsigned)(x0 + 1) < (unsigned)WW) ? lx : 0.f;

    int xp; float A, B;
    if (x0 < 0)        { xp = 0;   A = wx1; B = 0.f; }
    else if (x0 > 126) { xp = 126; A = 0.f; B = wx0; }
    else               { xp = x0;  A = wx0; B = wx1; }

    int y0c = min(max(y0, 0), HH - 1);
    int y1c = min(max(y0 + 1, 0), HH - 1);

    g_w4[idx]   = make_float4(wy0 * A, wy0 * B, wy1 * A, wy1 * B);
    g_meta[idx] = (unsigned)y0c | ((unsigned)y1c << 8) | ((unsigned)xp << 16);
}

// ---------------------------------------------------------------------------
// Kernel 3: grouped deformable conv — R3 gather structure on the ORIGINAL
// 16MB x array (L1-resident), weights/meta precomputed by bilin_kernel.
// grid (H, B); block (32, 8 groups); 4 px per thread.
// launch_bounds(256,2): regs<=128 -> 16 warps/SM (midpoint occupancy).
// ---------------------------------------------------------------------------
__global__ __launch_bounds__(256, 2) void deform_kernel(
    const float* __restrict__ x, const float* __restrict__ dw,
    const float* __restrict__ db, float* __restrict__ out)
{
    __shared__ __align__(16) float s_w[NGRP * 9 * CG * OG];  // [g][k][c][oo]

    int tx = threadIdx.x;
    int g  = threadIdx.y;
    int tid = g * 32 + tx;
    int b = blockIdx.y;
    int h = blockIdx.x;

    for (int i = tid; i < NGRP * 9 * CG * OG; i += 256) {
        int gg = i / 576;
        int r  = i - gg * 576;
        int k  = r >> 6;
        int rc = r & 63;
        int c  = rc >> 3;
        int oo = rc & 7;
        s_w[i] = dw[((gg * 8 + oo) * 8 + c) * 9 + k];
    }
    __syncthreads();

    const float* xb = x + (size_t)(b * CIN + g * CG) * HWSZ;

    unsigned long long acc2[4][4];
#pragma unroll
    for (int q = 0; q < 4; q++) {
        unsigned long long t = pk2(db[g * 8 + 2 * q], db[g * 8 + 2 * q + 1]);
        acc2[0][q] = t; acc2[1][q] = t; acc2[2][q] = t; acc2[3][q] = t;
    }

#pragma unroll 1
    for (int k = 0; k < 9; k++) {
        float4 w4[4];
        int o0[4], o1[4];
#pragma unroll
        for (int p = 0; p < 4; p++) {
            int wp = tx + 32 * p;
            int midx = ((b * 9 + k) * HH + h) * WW + wp;
            w4[p] = __ldg(&g_w4[midx]);
            unsigned meta = __ldg(&g_meta[midx]);
            int y0c =  meta        & 255;
            int y1c = (meta >> 8)  & 255;
            int xp  =  meta >> 16;
            o0[p] = (y0c << 7) + xp;
            o1[p] = (y1c << 7) + xp;
        }
        const float* wk = &s_w[(g * 9 + k) * 64];
#pragma unroll
        for (int c = 0; c < 8; c++) {
            ulonglong2 u0 = *(const ulonglong2*)(wk + c * 8);
            ulonglong2 u1 = *(const ulonglong2*)(wk + c * 8 + 4);
            const float* xc = xb + c * HWSZ;
#pragma unroll
            for (int p = 0; p < 4; p++) {
                float v = w4[p].x * __ldg(xc + o0[p])     +
                          w4[p].y * __ldg(xc + o0[p] + 1) +
                          w4[p].z * __ldg(xc + o1[p])     +
                          w4[p].w * __ldg(xc + o1[p] + 1);
                unsigned long long v2 = pk2(v, v);
                acc2[p][0] = ffma2(v2, u0.x, acc2[p][0]);
                acc2[p][1] = ffma2(v2, u0.y, acc2[p][1]);
                acc2[p][2] = ffma2(v2, u1.x, acc2[p][2]);
                acc2[p][3] = ffma2(v2, u1.y, acc2[p][3]);
            }
        }
    }

#pragma unroll
    for (int q = 0; q < 4; q++)
#pragma unroll
        for (int p = 0; p < 4; p++) {
            float v0, v1;
            upk2(acc2[p][q], v0, v1);
            int wp = tx + 32 * p;
            out[((b * CIN + g * 8 + 2 * q)     * HH + h) * WW + wp] = v0;
            out[((b * CIN + g * 8 + 2 * q + 1) * HH + h) * WW + wp] = v1;
        }
}

// ---------------------------------------------------------------------------
extern "C" void kernel_launch(void* const* d_in, const int* in_sizes, int n_in,
                              void* d_out, int out_size)
{
    const float* x  = (const float*)d_in[0];
    const float* ow = (const float*)d_in[1];
    const float* ob = (const float*)d_in[2];
    const float* pa = (const float*)d_in[3];
    const float* dw = (const float*)d_in[4];
    const float* db = (const float*)d_in[5];
    float* out = (float*)d_out;

    offset_conv_kernel<<<dim3(4, 16, 8), dim3(32, 4)>>>(x, ow, ob, pa);
    const int totB = BATCH * 9 * HWSZ;
    bilin_kernel<<<(totB + 255) / 256, 256>>>();
    deform_kernel<<<dim3(HH, BATCH), dim3(32, 8)>>>(x, dw, db, out);
}

// round 13
// speedup vs baseline: 1.4087x; 1.0486x over previous
#include <cuda_runtime.h>

#define BATCH 8
#define CIN   64
#define HH    128
#define WW    128
#define HWSZ  (HH * WW)
#define NGRP  8
#define CG    8
#define OG    8
#define OFFC  18

__device__ float g_part[2 * BATCH * OFFC * HWSZ];   // raw conv partial sums (no bias)

// ---- packed f32x2 helpers (Blackwell) -------------------------------------
__device__ __forceinline__ unsigned long long pk2(float lo, float hi) {
    unsigned long long r;
    asm("mov.b64 %0, {%1,%2};" : "=l"(r) : "f"(lo), "f"(hi));
    return r;
}
__device__ __forceinline__ void upk2(unsigned long long v, float& lo, float& hi) {
    asm("mov.b64 {%0,%1}, %2;" : "=f"(lo), "=f"(hi) : "l"(v));
}
__device__ __forceinline__ unsigned long long ffma2(
    unsigned long long a, unsigned long long b, unsigned long long c) {
    unsigned long long d;
    asm("fma.rn.f32x2 %0, %1, %2, %3;" : "=l"(d) : "l"(a), "l"(b), "l"(c));
    return d;
}

// ---------------------------------------------------------------------------
// Kernel 1: offset conv, SPLIT over input channels (32 per block).
// grid (4,16,16): z = b*2 + half. Block (32,4), 2 rows x 18 outputs/thread.
// Writes raw partial sums (no bias/prelu) to g_part[half].
// smem halves to 23KB -> ~2x resident blocks vs unsplit.
// ---------------------------------------------------------------------------
__global__ __launch_bounds__(128) void offset_conv_kernel(
    const float* __restrict__ x, const float* __restrict__ ow)
{
    __shared__ __align__(16) float ws[32 * 9 * 20];    // [c_local][tap][20], 23040 B

    int tx = threadIdx.x, ty = threadIdx.y;
    int tid = ty * 32 + tx;
    int bz = blockIdx.z;
    int b    = bz >> 1;
    int half = bz & 1;
    int c0   = half * 32;

    for (int i = tid; i < 32 * 9 * 18; i += 128) {
        int c = i / 162;
        int r = i - c * 162;
        int tap = r / 18;
        int j = r - tap * 18;
        ws[(c * 9 + tap) * 20 + j] = ow[j * (CIN * 9) + (c0 + c) * 9 + tap];
    }
    __syncthreads();

    int w0 = blockIdx.x * 32 + tx;
    int h0 = blockIdx.y * 8 + ty * 2;

    bool vr[4], vc[3];
#pragma unroll
    for (int r = 0; r < 4; r++) vr[r] = (unsigned)(h0 - 1 + r) < (unsigned)HH;
#pragma unroll
    for (int cc = 0; cc < 3; cc++) vc[cc] = (unsigned)(w0 - 1 + cc) < (unsigned)WW;

    unsigned long long acc2[2][9];
#pragma unroll
    for (int jj = 0; jj < 9; jj++) {
        acc2[0][jj] = 0ull;
        acc2[1][jj] = 0ull;
    }

    const float* xbase = x + ((size_t)(b * CIN + c0) * HH + (h0 - 1)) * WW + (w0 - 1);

    for (int c = 0; c < 32; c++) {
        const float* px = xbase + c * HWSZ;
        float xv[4][3];
#pragma unroll
        for (int r = 0; r < 4; r++)
#pragma unroll
            for (int cc = 0; cc < 3; cc++)
                xv[r][cc] = (vr[r] && vc[cc]) ? __ldg(px + r * WW + cc) : 0.f;

        const float* wrow = &ws[c * 180];
#pragma unroll
        for (int tap = 0; tap < 9; tap++) {
            const char* wp = (const char*)(wrow + tap * 20);
            ulonglong2 q0 = *(const ulonglong2*)(wp);
            ulonglong2 q1 = *(const ulonglong2*)(wp + 16);
            ulonglong2 q2 = *(const ulonglong2*)(wp + 32);
            ulonglong2 q3 = *(const ulonglong2*)(wp + 48);
            unsigned long long q8 = *(const unsigned long long*)(wp + 64);
            unsigned long long wj[9] = {q0.x, q0.y, q1.x, q1.y,
                                        q2.x, q2.y, q3.x, q3.y, q8};
            int ky = tap / 3;
            int kx = tap - ky * 3;
            unsigned long long a0 = pk2(xv[ky][kx],     xv[ky][kx]);
            unsigned long long a1 = pk2(xv[ky + 1][kx], xv[ky + 1][kx]);
#pragma unroll
            for (int jj = 0; jj < 9; jj++) {
                acc2[0][jj] = ffma2(a0, wj[jj], acc2[0][jj]);
                acc2[1][jj] = ffma2(a1, wj[jj], acc2[1][jj]);
            }
        }
    }

    float* gp = g_part + (size_t)(half * BATCH + b) * OFFC * HWSZ;
#pragma unroll
    for (int i = 0; i < 2; i++)
#pragma unroll
        for (int jj = 0; jj < 9; jj++) {
            float v0, v1;
            upk2(acc2[i][jj], v0, v1);
            int hrow = h0 + i;
            gp[(2 * jj)     * HWSZ + hrow * WW + w0] = v0;
            gp[(2 * jj + 1) * HWSZ + hrow * WW + w0] = v1;
        }
}

// ---------------------------------------------------------------------------
// Kernel 2: grouped deformable conv.
// Phase 1 (in-block): combine conv partials + bias + PReLU -> offsets, then
// bilinear precompute with xp-remap: w4=(wy0*A,wy0*B,wy1*A,wy1*B),
// meta = y0c | y1c<<8 | xp<<16, into smem for this row.
// Phase 2: R11's measured hot loop (4 px/thread, 2 base offsets, 4 LDG.32).
// grid (H, B); block (32, 8 groups). launch_bounds(256,2) -> 16 warps/SM.
// ---------------------------------------------------------------------------
__global__ __launch_bounds__(256, 2) void deform_kernel(
    const float* __restrict__ x, const float* __restrict__ dw,
    const float* __restrict__ db, const float* __restrict__ ob,
    const float* __restrict__ pa, float* __restrict__ out)
{
    __shared__ __align__(16) float s_w[NGRP * 9 * CG * OG];  // 18432 B
    __shared__ __align__(16) float4 s_tw[9 * WW];            // 18432 B
    __shared__ unsigned s_to[9 * WW];                        //  4608 B

    int tx = threadIdx.x;
    int g  = threadIdx.y;
    int tid = g * 32 + tx;
    int b = blockIdx.y;
    int h = blockIdx.x;

    // stage dconv weights: s_w[g][k][c][oo]
    for (int i = tid; i < NGRP * 9 * CG * OG; i += 256) {
        int gg = i / 576;
        int r  = i - gg * 576;
        int k  = r >> 6;
        int rc = r & 63;
        int c  = rc >> 3;
        int oo = rc & 7;
        s_w[i] = dw[((gg * 8 + oo) * 8 + c) * 9 + k];
    }

    // phase 1: combine partials + bias + prelu, bilinear precompute
    {
        float a = pa[0];
        const float* p0 = g_part + (size_t)b * OFFC * HWSZ + (size_t)h * WW;
        const float* p1 = p0 + (size_t)BATCH * OFFC * HWSZ;
        for (int i = tid; i < 9 * WW; i += 256) {
            int k = i >> 7;
            int w = i & 127;
            float dy = p0[(2 * k) * HWSZ + w] + p1[(2 * k) * HWSZ + w] + ob[2 * k];
            float dx = p0[(2 * k + 1) * HWSZ + w] + p1[(2 * k + 1) * HWSZ + w] + ob[2 * k + 1];
            dy = dy > 0.f ? dy : a * dy;
            dx = dx > 0.f ? dx : a * dx;
            int ky = k / 3 - 1;
            int kx = k - (k / 3) * 3 - 1;
            float py = (float)(h + ky) + dy;
            float px = (float)(w + kx) + dx;
            float y0f = floorf(py), x0f = floorf(px);
            float ly = py - y0f, lx = px - x0f;
            int y0 = (int)y0f, x0 = (int)x0f;
            float hy = 1.f - ly, hx = 1.f - lx;
            float wy0 = ((unsigned)y0       < (unsigned)HH) ? hy : 0.f;
            float wy1 = ((unsigned)(y0 + 1) < (unsigned)HH) ? ly : 0.f;
            float wx0 = ((unsigned)x0       < (unsigned)WW) ? hx : 0.f;
            float wx1 = ((unsigned)(x0 + 1) < (unsigned)WW) ? lx : 0.f;
            int xp; float A, B;
            if (x0 < 0)        { xp = 0;   A = wx1; B = 0.f; }
            else if (x0 > 126) { xp = 126; A = 0.f; B = wx0; }
            else               { xp = x0;  A = wx0; B = wx1; }
            int y0c = min(max(y0, 0), HH - 1);
            int y1c = min(max(y0 + 1, 0), HH - 1);
            s_tw[i] = make_float4(wy0 * A, wy0 * B, wy1 * A, wy1 * B);
            s_to[i] = (unsigned)y0c | ((unsigned)y1c << 8) | ((unsigned)xp << 16);
        }
    }
    __syncthreads();

    const float* xb = x + (size_t)(b * CIN + g * CG) * HWSZ;

    unsigned long long acc2[4][4];
#pragma unroll
    for (int q = 0; q < 4; q++) {
        unsigned long long t = pk2(db[g * 8 + 2 * q], db[g * 8 + 2 * q + 1]);
        acc2[0][q] = t; acc2[1][q] = t; acc2[2][q] = t; acc2[3][q] = t;
    }

#pragma unroll 1
    for (int k = 0; k < 9; k++) {
        float4 w4[4];
        int o0[4], o1[4];
#pragma unroll
        for (int p = 0; p < 4; p++) {
            int wp = tx + 32 * p;
            w4[p] = s_tw[(k << 7) + wp];
            unsigned meta = s_to[(k << 7) + wp];
            int y0c =  meta        & 255;
            int y1c = (meta >> 8)  & 255;
            int xp  =  meta >> 16;
            o0[p] = (y0c << 7) + xp;
            o1[p] = (y1c << 7) + xp;
        }
        const float* wk = &s_w[(g * 9 + k) * 64];
#pragma unroll
        for (int c = 0; c < 8; c++) {
            ulonglong2 u0 = *(const ulonglong2*)(wk + c * 8);
            ulonglong2 u1 = *(const ulonglong2*)(wk + c * 8 + 4);
            const float* xc = xb + c * HWSZ;
#pragma unroll
            for (int p = 0; p < 4; p++) {
                float v = w4[p].x * __ldg(xc + o0[p])     +
                          w4[p].y * __ldg(xc + o0[p] + 1) +
                          w4[p].z * __ldg(xc + o1[p])     +
                          w4[p].w * __ldg(xc + o1[p] + 1);
                unsigned long long v2 = pk2(v, v);
                acc2[p][0] = ffma2(v2, u0.x, acc2[p][0]);
                acc2[p][1] = ffma2(v2, u0.y, acc2[p][1]);
                acc2[p][2] = ffma2(v2, u1.x, acc2[p][2]);
                acc2[p][3] = ffma2(v2, u1.y, acc2[p][3]);
            }
        }
    }

#pragma unroll
    for (int q = 0; q < 4; q++)
#pragma unroll
        for (int p = 0; p < 4; p++) {
            float v0, v1;
            upk2(acc2[p][q], v0, v1);
            int wp = tx + 32 * p;
            out[((b * CIN + g * 8 + 2 * q)     * HH + h) * WW + wp] = v0;
            out[((b * CIN + g * 8 + 2 * q + 1) * HH + h) * WW + wp] = v1;
        }
}

// ---------------------------------------------------------------------------
extern "C" void kernel_launch(void* const* d_in, const int* in_sizes, int n_in,
                              void* d_out, int out_size)
{
    const float* x  = (const float*)d_in[0];
    const float* ow = (const float*)d_in[1];
    const float* ob = (const float*)d_in[2];
    const float* pa = (const float*)d_in[3];
    const float* dw = (const float*)d_in[4];
    const float* db = (const float*)d_in[5];
    float* out = (float*)d_out;

    offset_conv_kernel<<<dim3(4, 16, 16), dim3(32, 4)>>>(x, ow);
    deform_kernel<<<dim3(HH, BATCH), dim3(32, 8)>>>(x, dw, db, ob, pa, out);
}